// round 1
// baseline (speedup 1.0000x reference)
#include <cuda_runtime.h>
#include <math.h>

// Problem constants (fixed shapes in registry)
#define BN 8192
#define DN 2048
#define TINV 10.0f   // 1/T, T = 0.1

// Scratch (device globals -> no allocation in kernel_launch)
__device__ float g_a[DN];      // normalized anchor
__device__ float g_na;         // max(||a||, 1e-6)
__device__ float g_neg[BN];    // -cos_j / T

// ---------------------------------------------------------------------------
// Kernel A: normalize embed row 0, compute na = max(||a||, 1e-6)
// 1 block, 256 threads. Tiny; latency-bound.
// ---------------------------------------------------------------------------
__global__ void prep_kernel(const float* __restrict__ embed) {
    __shared__ float red[32];
    const int tid = threadIdx.x;
    const int nwarps = blockDim.x >> 5;

    // pass 1: ||embed[0]||^2
    float s = 0.f;
    for (int i = tid; i < DN; i += blockDim.x) {
        float v = embed[i];
        s = fmaf(v, v, s);
    }
    #pragma unroll
    for (int o = 16; o; o >>= 1) s += __shfl_xor_sync(0xffffffffu, s, o);
    if ((tid & 31) == 0) red[tid >> 5] = s;
    __syncthreads();
    if (tid < 32) {
        float v = (tid < nwarps) ? red[tid] : 0.f;
        #pragma unroll
        for (int o = 16; o; o >>= 1) v += __shfl_xor_sync(0xffffffffu, v, o);
        if (tid == 0) red[0] = v;
    }
    __syncthreads();
    const float inv = 1.0f / fmaxf(sqrtf(red[0]), 1e-12f);
    __syncthreads();  // everyone has read red[0] before it is reused

    // pass 2: write a, accumulate ||a||^2 (faithful to reference's na)
    float s2 = 0.f;
    for (int i = tid; i < DN; i += blockDim.x) {
        float a = embed[i] * inv;
        g_a[i] = a;
        s2 = fmaf(a, a, s2);
    }
    #pragma unroll
    for (int o = 16; o; o >>= 1) s2 += __shfl_xor_sync(0xffffffffu, s2, o);
    if ((tid & 31) == 0) red[tid >> 5] = s2;
    __syncthreads();
    if (tid == 0) {
        float v = 0.f;
        for (int i = 0; i < nwarps; i++) v += red[i];
        g_na = fmaxf(sqrtf(v), 1e-6f);
    }
}

// ---------------------------------------------------------------------------
// Kernel B: one warp per row of embed_enhance.
// 512 blocks x 512 threads (16 warps -> 16 rows per block).
// Anchor staged in shared once per block (keeps L2 traffic ~= HBM traffic).
// neg[j] = -(dot(x_j, a) / (na * max(||x_j||, 1e-6))) / T
// ---------------------------------------------------------------------------
__global__ void __launch_bounds__(512) dot_kernel(const float* __restrict__ ee) {
    __shared__ float4 sa[DN / 4];   // 8 KB

    const int tid = threadIdx.x;
    const float4* ga4 = reinterpret_cast<const float4*>(g_a);
    for (int i = tid; i < DN / 4; i += blockDim.x) sa[i] = ga4[i];
    __syncthreads();

    const int warp = tid >> 5;
    const int lane = tid & 31;
    const int row  = blockIdx.x * (blockDim.x >> 5) + warp;

    const float4* x4 = reinterpret_cast<const float4*>(ee + (size_t)row * DN);

    float dot = 0.f, n2 = 0.f;
    #pragma unroll
    for (int i = 0; i < DN / (4 * 32); i++) {   // 16 iterations
        float4 x = x4[i * 32 + lane];
        float4 a = sa[i * 32 + lane];
        dot = fmaf(x.x, a.x, dot);
        dot = fmaf(x.y, a.y, dot);
        dot = fmaf(x.z, a.z, dot);
        dot = fmaf(x.w, a.w, dot);
        n2  = fmaf(x.x, x.x, n2);
        n2  = fmaf(x.y, x.y, n2);
        n2  = fmaf(x.z, x.z, n2);
        n2  = fmaf(x.w, x.w, n2);
    }
    #pragma unroll
    for (int o = 16; o; o >>= 1) {
        dot += __shfl_xor_sync(0xffffffffu, dot, o);
        n2  += __shfl_xor_sync(0xffffffffu, n2,  o);
    }
    if (lane == 0) {
        float nb  = fmaxf(sqrtf(n2), 1e-6f);
        float neg = -TINV * dot / (g_na * nb);
        g_neg[row] = neg;
    }
}

// ---------------------------------------------------------------------------
// Kernel C: final scalar. 1 block, 1024 threads, double accumulation.
// L0 = sum_{j!=0} -Cij*(neg_j - log(E0))
//    = (l0/C0) * ( log(E0)*sum_l  -  sum_{l*neg} )
// ---------------------------------------------------------------------------
__global__ void finish_kernel(const float* __restrict__ labels,
                              float* __restrict__ out) {
    __shared__ double redE[32], redW[32], redL[32];
    const int tid = threadIdx.x;
    const int nwarps = blockDim.x >> 5;
    const float l0 = labels[0];

    double E = 0.0, Wneg = 0.0, Lsum = 0.0;
    for (int j = tid; j < BN; j += blockDim.x) {
        if (j == 0) continue;
        float neg = g_neg[j];
        float lj  = labels[j];
        E    += (double)expf(neg);
        Wneg += (double)lj * (double)neg;
        Lsum += (double)lj;
    }
    #pragma unroll
    for (int o = 16; o; o >>= 1) {
        E    += __shfl_xor_sync(0xffffffffu, E,    o);
        Wneg += __shfl_xor_sync(0xffffffffu, Wneg, o);
        Lsum += __shfl_xor_sync(0xffffffffu, Lsum, o);
    }
    if ((tid & 31) == 0) {
        redE[tid >> 5] = E; redW[tid >> 5] = Wneg; redL[tid >> 5] = Lsum;
    }
    __syncthreads();
    if (tid == 0) {
        double Et = 0, Wt = 0, Lt = 0;
        for (int i = 0; i < nwarps; i++) { Et += redE[i]; Wt += redW[i]; Lt += redL[i]; }
        double E0   = 1e-12 + Et;
        double C0   = 1e-12 + (double)l0 * Lt;
        double logE = log(E0);
        double L0   = ((double)l0 / C0) * (logE * Lt - Wt);
        out[0] = (float)(L0 / (double)BN);
    }
}

// ---------------------------------------------------------------------------
extern "C" void kernel_launch(void* const* d_in, const int* in_sizes, int n_in,
                              void* d_out, int out_size) {
    const float* embed         = (const float*)d_in[0];
    const float* embed_enhance = (const float*)d_in[1];
    const float* labels        = (const float*)d_in[2];
    float* out = (float*)d_out;

    prep_kernel<<<1, 256>>>(embed);
    dot_kernel<<<BN / 16, 512>>>(embed_enhance);
    finish_kernel<<<1, 1024>>>(labels, out);
}

// round 2
// speedup vs baseline: 1.7805x; 1.7805x over previous
#include <cuda_runtime.h>
#include <math.h>

// Fixed shapes
#define BN 8192
#define DN 2048
#define TINV 10.0f          // 1/T, T = 0.1
#define NBLK 512            // blocks
#define NTHR 512            // threads/block -> 16 warps -> 16 rows/block
#define WPB (NTHR / 32)     // 16

// Scratch (device globals; zero-initialized at module load)
__device__ double g_partE[NBLK];
__device__ double g_partW[NBLK];
__device__ double g_partL[NBLK];
__device__ unsigned int g_count;   // reset to 0 by the last block each launch

__device__ __forceinline__ float warp_sum(float v) {
    #pragma unroll
    for (int o = 16; o; o >>= 1) v += __shfl_xor_sync(0xffffffffu, v, o);
    return v;
}
__device__ __forceinline__ double warp_sum_d(double v) {
    #pragma unroll
    for (int o = 16; o; o >>= 1) v += __shfl_xor_sync(0xffffffffu, v, o);
    return v;
}

__global__ void __launch_bounds__(NTHR)
fused_kernel(const float* __restrict__ embed,
             const float* __restrict__ ee,
             const float* __restrict__ labels,
             float* __restrict__ out) {
    __shared__ float4  sa[DN / 4];      // normalized anchor, 8 KB
    __shared__ float   redf[WPB];
    __shared__ double  redE[WPB], redW[WPB], redL[WPB];
    __shared__ float   s_scale;         // 1 / (na) combined below
    __shared__ bool    s_last;

    const int tid  = threadIdx.x;
    const int warp = tid >> 5;
    const int lane = tid & 31;

    // ---- Phase 1: recompute normalized anchor per block (8 KB from L2) ----
    const float4* e4 = reinterpret_cast<const float4*>(embed);
    float4 ev[DN / 4 / NTHR];           // 1 float4 per thread (2048/4/512 = 1)
    float s = 0.f;
    {
        float4 v = e4[tid];
        ev[0] = v;
        s = v.x * v.x + v.y * v.y + v.z * v.z + v.w * v.w;
    }
    s = warp_sum(s);
    if (lane == 0) redf[warp] = s;
    __syncthreads();
    if (warp == 0) {
        float v = (lane < WPB) ? redf[lane] : 0.f;
        v = warp_sum(v);
        if (lane == 0) redf[0] = v;
    }
    __syncthreads();
    const float inv = 1.0f / fmaxf(sqrtf(redf[0]), 1e-12f);
    __syncthreads();   // everyone read redf[0]

    // normalized anchor into shared; accumulate ||a||^2 for na (faithful)
    float4 a;
    a.x = ev[0].x * inv; a.y = ev[0].y * inv; a.z = ev[0].z * inv; a.w = ev[0].w * inv;
    sa[tid] = a;
    float s2 = a.x * a.x + a.y * a.y + a.z * a.z + a.w * a.w;
    s2 = warp_sum(s2);
    if (lane == 0) redf[warp] = s2;
    __syncthreads();
    if (tid == 0) {
        float v = 0.f;
        #pragma unroll
        for (int i = 0; i < WPB; i++) v += redf[i];
        float na = fmaxf(sqrtf(v), 1e-6f);
        s_scale = TINV / na;            // neg = -(scale) * dot / nb
    }
    __syncthreads();
    const float scale = s_scale;

    // ---- Phase 2: one warp per row, 16 rows per block ----
    const int row = blockIdx.x * WPB + warp;
    const float4* x4 = reinterpret_cast<const float4*>(ee + (size_t)row * DN);

    float dot = 0.f, n2 = 0.f;
    #pragma unroll
    for (int i = 0; i < DN / (4 * 32); i++) {   // 16 float4 loads per lane
        float4 x = x4[i * 32 + lane];
        float4 aa = sa[i * 32 + lane];
        dot = fmaf(x.x, aa.x, dot);
        dot = fmaf(x.y, aa.y, dot);
        dot = fmaf(x.z, aa.z, dot);
        dot = fmaf(x.w, aa.w, dot);
        n2  = fmaf(x.x, x.x, n2);
        n2  = fmaf(x.y, x.y, n2);
        n2  = fmaf(x.z, x.z, n2);
        n2  = fmaf(x.w, x.w, n2);
    }
    dot = warp_sum(dot);
    n2  = warp_sum(n2);

    // lane 0 of each warp: compute neg and the three contributions
    if (lane == 0) {
        double E = 0.0, W = 0.0, L = 0.0;
        if (row != 0) {
            float nb  = fmaxf(sqrtf(n2), 1e-6f);
            float neg = -scale * dot / nb;
            float lj  = labels[row];
            E = (double)expf(neg);
            W = (double)lj * (double)neg;
            L = (double)lj;
        }
        redE[warp] = E; redW[warp] = W; redL[warp] = L;
    }
    __syncthreads();

    // block-level partials -> scratch slot
    if (warp == 0) {
        double E = (lane < WPB) ? redE[lane] : 0.0;
        double W = (lane < WPB) ? redW[lane] : 0.0;
        double L = (lane < WPB) ? redL[lane] : 0.0;
        E = warp_sum_d(E); W = warp_sum_d(W); L = warp_sum_d(L);
        if (lane == 0) {
            g_partE[blockIdx.x] = E;
            g_partW[blockIdx.x] = W;
            g_partL[blockIdx.x] = L;
            __threadfence();
            unsigned int c = atomicAdd(&g_count, 1u);
            s_last = (c == NBLK - 1);
        }
    }
    __syncthreads();

    // ---- Phase 3: last block reduces 512 partials and finalizes ----
    if (s_last) {
        double E = 0.0, W = 0.0, L = 0.0;
        if (tid < NBLK) {                // 512 threads -> one slot each
            E = g_partE[tid]; W = g_partW[tid]; L = g_partL[tid];
        }
        E = warp_sum_d(E); W = warp_sum_d(W); L = warp_sum_d(L);
        if (lane == 0) { redE[warp] = E; redW[warp] = W; redL[warp] = L; }
        __syncthreads();
        if (tid == 0) {
            double Et = 0, Wt = 0, Lt = 0;
            #pragma unroll
            for (int i = 0; i < WPB; i++) { Et += redE[i]; Wt += redW[i]; Lt += redL[i]; }
            double l0   = (double)labels[0];
            double E0   = 1e-12 + Et;
            double C0   = 1e-12 + l0 * Lt;
            double logE = log(E0);
            double L0   = (l0 / C0) * (logE * Lt - Wt);
            out[0] = (float)(L0 / (double)BN);
            g_count = 0;                 // reset for next graph replay
        }
    }
}

extern "C" void kernel_launch(void* const* d_in, const int* in_sizes, int n_in,
                              void* d_out, int out_size) {
    const float* embed         = (const float*)d_in[0];
    const float* embed_enhance = (const float*)d_in[1];
    const float* labels        = (const float*)d_in[2];
    float* out = (float*)d_out;

    fused_kernel<<<NBLK, NTHR>>>(embed, embed_enhance, labels, out);
}